// round 10
// baseline (speedup 1.0000x reference)
#include <cuda_runtime.h>
#include <cuda_fp16.h>
#include <cstdint>

// RNN-T Joiner: hybrid tensor+FFMA pipe GEMM (R9 fixed: FFMA A-producer chunk
// addressing was aq0,aq0+2 instead of aq0,aq0+1 -> uninitialized smem NaN).
//   prep_a: A_half[m,k] = fp16(tanh(src+tgt))  (164 MB scratch)
//   prep_w: W -> fp16                           (1 MB scratch)
//   hybrid: per m-chunk (128 rows), 15 CTAs:
//     bx 0..6  : tensor path, n0 = bx*128  (mma m16n8k16, rt16 floor)
//     bx 7..14 : FFMA path,  n0 = 896 + (bx-7)*16  (fp32 SIMT, FMA pipe)
// M = 160000, K = 512, N = 1024.

constexpr int Bb = 4, Tt = 400, Uu = 100, Dd = 512, Vv = 1024;
constexpr long long Mm = (long long)Bb * Tt * Uu;   // 160000 = 128*1250

#define BM 128
#define BN 128
#define BK 32
#define NCH (Dd / BK)        // 16
#define STG 4                // tensor-path cp.async stages
#define RST 40               // smem row stride in halfs (80B): conflict-free
#define NT_CTAS 7            // tensor CTAs per m-chunk (n = 0..895)
#define BNF 16               // FFMA path n per CTA (n = 896..1023, 8 CTAs)

__device__ __half A_half[(size_t)Mm * Dd];   // 164 MB scratch (sanctioned)
__device__ __half W_half[(size_t)Vv * Dd];   // 1 MB

__device__ __forceinline__ float fast_tanh(float x) {
    float y; asm("tanh.approx.f32 %0, %1;" : "=f"(y) : "f"(x)); return y;
}
__device__ __forceinline__ uint32_t smem_u32(const void* p) {
    uint32_t a;
    asm("{ .reg .u64 t; cvta.to.shared.u64 t, %1; cvt.u32.u64 %0, t; }" : "=r"(a) : "l"(p));
    return a;
}
__device__ __forceinline__ void mma_fp16(float* d, const uint32_t* a,
                                         uint32_t b0, uint32_t b1) {
    asm volatile(
        "mma.sync.aligned.m16n8k16.row.col.f32.f16.f16.f32 "
        "{%0,%1,%2,%3}, {%4,%5,%6,%7}, {%8,%9}, {%0,%1,%2,%3};"
        : "+f"(d[0]), "+f"(d[1]), "+f"(d[2]), "+f"(d[3])
        : "r"(a[0]), "r"(a[1]), "r"(a[2]), "r"(a[3]), "r"(b0), "r"(b1));
}
__device__ __forceinline__ void ldm_x4(uint32_t* r, uint32_t addr) {
    asm volatile("ldmatrix.sync.aligned.m8n8.x4.shared.b16 {%0,%1,%2,%3}, [%4];"
                 : "=r"(r[0]), "=r"(r[1]), "=r"(r[2]), "=r"(r[3]) : "r"(addr));
}

// ---------------- Phase 1a: A = fp16(tanh(src + tgt)), 16 elems/thread ----
__global__ __launch_bounds__(256)
void prep_a_kernel(const float* __restrict__ src, const float* __restrict__ tgt) {
    size_t idx = (size_t)blockIdx.x * 256 + threadIdx.x;   // one per 16 elems
    int m = (int)(idx >> 5);
    int kv = ((int)idx & 31) * 16;
    int b = m / (Tt * Uu);
    int rem = m - b * (Tt * Uu);
    int t = rem / Uu;
    int u = rem - t * Uu;
    const float* sp = src + ((size_t)b * Tt + t) * Dd + kv;
    const float* tp = tgt + ((size_t)b * Uu + u) * Dd + kv;
    __half2 h[8];
#pragma unroll
    for (int q = 0; q < 4; q++) {
        float4 s0 = *reinterpret_cast<const float4*>(sp + q * 4);
        float4 t0 = *reinterpret_cast<const float4*>(tp + q * 4);
        h[q * 2 + 0] = __floats2half2_rn(fast_tanh(s0.x + t0.x), fast_tanh(s0.y + t0.y));
        h[q * 2 + 1] = __floats2half2_rn(fast_tanh(s0.z + t0.z), fast_tanh(s0.w + t0.w));
    }
    __half* dst = &A_half[(size_t)m * Dd + kv];
    *reinterpret_cast<uint4*>(dst) = *reinterpret_cast<uint4*>(&h[0]);
    *reinterpret_cast<uint4*>(dst + 8) = *reinterpret_cast<uint4*>(&h[4]);
}

// ---------------- Phase 1b: W -> fp16 ----------------
__global__ __launch_bounds__(256)
void prep_w_kernel(const float* __restrict__ W) {
    size_t idx = ((size_t)blockIdx.x * 256 + threadIdx.x) * 8;
    float4 w0 = *reinterpret_cast<const float4*>(W + idx);
    float4 w1 = *reinterpret_cast<const float4*>(W + idx + 4);
    __half2 h[4];
    h[0] = __floats2half2_rn(w0.x, w0.y);
    h[1] = __floats2half2_rn(w0.z, w0.w);
    h[2] = __floats2half2_rn(w1.x, w1.y);
    h[3] = __floats2half2_rn(w1.z, w1.w);
    *reinterpret_cast<uint4*>(&W_half[idx]) = *reinterpret_cast<uint4*>(h);
}

// ---------------- Phase 2: hybrid GEMM ----------------
constexpr int STAGE_H = BM * RST;                   // 5120 halfs / stage
constexpr int SMEM_TOTAL = 2 * STG * STAGE_H * 2;   // 81920 B (tensor path max)

// FFMA-path smem layout (within the same dynamic smem block)
constexpr int FA_STG_B = BM * (RST * 2);            // A stage: 128 rows * 80B = 10240
constexpr int FW_STRIDE = 20;                       // W row stride (floats)
constexpr int FW_STG_F = BK * FW_STRIDE;            // 640 floats per W stage

__global__ __launch_bounds__(256, 2)
void joiner_gemm_hybrid(const float* __restrict__ W, const float* __restrict__ bias,
                        float* __restrict__ out) {
    extern __shared__ __half sm[];
    const int tid = threadIdx.x;
    const size_t m0 = (size_t)blockIdx.y * BM;
    const int bx = blockIdx.x;

    if (bx < NT_CTAS) {
        // ================= TENSOR PATH (n0 = bx*128) =================
        __half* Asm = sm;
        __half* Bsm = sm + STG * STAGE_H;
        const int wid = tid >> 5, lid = tid & 31;
        const int g = lid >> 2, c = lid & 3;
        const int wm = wid >> 2, wn = wid & 3;
        const int n0 = bx * BN;

        const int r = tid >> 1;
        const int h = tid & 1;
        const __half* agp = A_half + (m0 + r) * Dd + h * 16;
        const __half* bgp = W_half + (size_t)(n0 + r) * Dd + h * 16;
        const uint32_t a_dst0 = smem_u32(Asm) + (uint32_t)(r * (RST * 2) + h * 32);
        const uint32_t b_dst0 = smem_u32(Bsm) + (uint32_t)(r * (RST * 2) + h * 32);

        const uint32_t a_lm = smem_u32(Asm)
            + (uint32_t)((wm * 64 + (lid & 15)) * (RST * 2) + ((lid >> 4) & 1) * 16);
        const uint32_t b_lm = smem_u32(Bsm)
            + (uint32_t)((wn * 32 + ((lid >> 4) & 1) * 8 + (lid & 7)) * (RST * 2)
                         + ((lid >> 3) & 1) * 16);

        float acc[4][4][4];
#pragma unroll
        for (int mt = 0; mt < 4; mt++)
#pragma unroll
            for (int nt = 0; nt < 4; nt++)
#pragma unroll
                for (int i = 0; i < 4; i++) acc[mt][nt][i] = 0.0f;

#define ISSUE_STAGE(CH) do {                                                    \
        int st_ = (CH) & (STG - 1);                                             \
        const __half* ag_ = agp + (CH) * BK;                                    \
        const __half* bg_ = bgp + (CH) * BK;                                    \
        uint32_t ad_ = a_dst0 + st_ * (STAGE_H * 2);                            \
        uint32_t bd_ = b_dst0 + st_ * (STAGE_H * 2);                            \
        asm volatile(                                                           \
            "cp.async.cg.shared.global [%0], [%1], 16;\n"                       \
            "cp.async.cg.shared.global [%2], [%3], 16;\n"                       \
            "cp.async.cg.shared.global [%4], [%5], 16;\n"                       \
            "cp.async.cg.shared.global [%6], [%7], 16;\n"                       \
            "cp.async.commit_group;"                                            \
            :: "r"(ad_), "l"(ag_), "r"(ad_ + 16), "l"(ag_ + 8),                 \
               "r"(bd_), "l"(bg_), "r"(bd_ + 16), "l"(bg_ + 8) : "memory");     \
    } while (0)

        ISSUE_STAGE(0); ISSUE_STAGE(1); ISSUE_STAGE(2);

        for (int ch = 0; ch < NCH; ch++) {
            const int rem = NCH - 1 - ch;
            if (rem >= 2)      asm volatile("cp.async.wait_group 2;" ::: "memory");
            else if (rem == 1) asm volatile("cp.async.wait_group 1;" ::: "memory");
            else               asm volatile("cp.async.wait_group 0;" ::: "memory");
            __syncthreads();
            if (ch + 3 < NCH) ISSUE_STAGE(ch + 3);

            const int st = ch & (STG - 1);
            const uint32_t a_st = a_lm + st * (STAGE_H * 2);
            const uint32_t b_st = b_lm + st * (STAGE_H * 2);
#pragma unroll
            for (int ks = 0; ks < 2; ks++) {
                const int kbB = ks * 32;
                uint32_t a[4][4];
#pragma unroll
                for (int mt = 0; mt < 4; mt++)
                    ldm_x4(a[mt], a_st + mt * 16 * (RST * 2) + kbB);
                uint32_t b[2][4];
                ldm_x4(b[0], b_st + kbB);
                ldm_x4(b[1], b_st + 16 * (RST * 2) + kbB);
#pragma unroll
                for (int nt = 0; nt < 4; nt++) {
                    uint32_t b0 = b[nt >> 1][(nt & 1) * 2];
                    uint32_t b1 = b[nt >> 1][(nt & 1) * 2 + 1];
#pragma unroll
                    for (int mt = 0; mt < 4; mt++)
                        mma_fp16(acc[mt][nt], a[mt], b0, b1);
                }
            }
        }

#pragma unroll
        for (int nt = 0; nt < 4; nt++) {
            const int col = n0 + wn * 32 + nt * 8 + 2 * c;
            const float2 bz = *reinterpret_cast<const float2*>(bias + col);
#pragma unroll
            for (int mt = 0; mt < 4; mt++) {
                const size_t row = m0 + wm * 64 + mt * 16 + g;
                float2 o1, o2;
                o1.x = acc[mt][nt][0] + bz.x;
                o1.y = acc[mt][nt][1] + bz.y;
                o2.x = acc[mt][nt][2] + bz.x;
                o2.y = acc[mt][nt][3] + bz.y;
                *reinterpret_cast<float2*>(out + row * Vv + col) = o1;
                *reinterpret_cast<float2*>(out + (row + 8) * Vv + col) = o2;
            }
        }
    } else {
        // ================= FFMA PATH (n0 = 896 + (bx-7)*16) =================
        // A: fp16 [m][k] 2 stages (80B row stride); W: fp32 [k][n] 2 stages.
        __half* Af = sm;                                       // 2 x 10240 B
        float* Wf = reinterpret_cast<float*>(sm + 2 * (FA_STG_B / 2));
        const int n0 = NT_CTAS * BN + (bx - NT_CTAS) * BNF;

        const int tm = tid >> 2;       // 0..63 -> m rows {2tm, 2tm+1}
        const int tn = tid & 3;        // 0..3  -> n cols {4tn..4tn+3}

        // producers: 2 threads per A row; each covers 2 adjacent 16B chunks
        const int ar = tid >> 1;               // row 0..127
        const int aq0 = (tid & 1) * 2;         // chunk pair base: 0 or 2
        const __half* agp = A_half + (m0 + ar) * Dd;
        const uint32_t af_dst = smem_u32(Af) + (uint32_t)(ar * (RST * 2));

        float acc[2][4];
#pragma unroll
        for (int i = 0; i < 2; i++)
#pragma unroll
            for (int j = 0; j < 4; j++) acc[i][j] = 0.0f;

#define F_ISSUE_A(CH, S) do {                                                   \
        const __half* ag_ = agp + (CH) * BK + aq0 * 8;                          \
        uint32_t ad_ = af_dst + (S) * FA_STG_B + aq0 * 16;                      \
        asm volatile(                                                           \
            "cp.async.cg.shared.global [%0], [%1], 16;\n"                       \
            "cp.async.cg.shared.global [%2], [%3], 16;\n"                       \
            "cp.async.commit_group;"                                            \
            :: "r"(ad_), "l"(ag_), "r"(ad_ + 16), "l"(ag_ + 8) : "memory");     \
    } while (0)
#define F_STORE_W(CH, S) do {                                                   \
        for (int i_ = 0; i_ < 2; i_++) {                                        \
            int e_ = tid * 2 + i_;                                              \
            int kk_ = e_ & 31, nn_ = e_ >> 5;                                   \
            Wf[(S) * FW_STG_F + kk_ * FW_STRIDE + nn_] =                        \
                W[(size_t)(n0 + nn_) * Dd + (CH) * BK + kk_];                   \
        }                                                                       \
    } while (0)

        F_ISSUE_A(0, 0);
        F_STORE_W(0, 0);

        for (int ch = 0; ch < NCH; ch++) {
            const int s = ch & 1;
            asm volatile("cp.async.wait_group 0;" ::: "memory");
            __syncthreads();
            if (ch + 1 < NCH) {
                F_ISSUE_A(ch + 1, s ^ 1);
                F_STORE_W(ch + 1, s ^ 1);
            }
            const __half* a_st = Af + s * (FA_STG_B / 2);
            const float* w_st = Wf + s * FW_STG_F;
#pragma unroll
            for (int k8 = 0; k8 < 4; k8++) {
                uint4 a0r = *reinterpret_cast<const uint4*>(
                    a_st + (2 * tm) * RST + k8 * 8);
                uint4 a1r = *reinterpret_cast<const uint4*>(
                    a_st + (2 * tm + 1) * RST + k8 * 8);
                const __half2* a0h = reinterpret_cast<const __half2*>(&a0r);
                const __half2* a1h = reinterpret_cast<const __half2*>(&a1r);
                float a0f[8], a1f[8];
#pragma unroll
                for (int q = 0; q < 4; q++) {
                    float2 f0 = __half22float2(a0h[q]);
                    float2 f1 = __half22float2(a1h[q]);
                    a0f[q * 2] = f0.x; a0f[q * 2 + 1] = f0.y;
                    a1f[q * 2] = f1.x; a1f[q * 2 + 1] = f1.y;
                }
#pragma unroll
                for (int kk = 0; kk < 8; kk++) {
                    float4 w4 = *reinterpret_cast<const float4*>(
                        w_st + (k8 * 8 + kk) * FW_STRIDE + tn * 4);
                    acc[0][0] = fmaf(a0f[kk], w4.x, acc[0][0]);
                    acc[0][1] = fmaf(a0f[kk], w4.y, acc[0][1]);
                    acc[0][2] = fmaf(a0f[kk], w4.z, acc[0][2]);
                    acc[0][3] = fmaf(a0f[kk], w4.w, acc[0][3]);
                    acc[1][0] = fmaf(a1f[kk], w4.x, acc[1][0]);
                    acc[1][1] = fmaf(a1f[kk], w4.y, acc[1][1]);
                    acc[1][2] = fmaf(a1f[kk], w4.z, acc[1][2]);
                    acc[1][3] = fmaf(a1f[kk], w4.w, acc[1][3]);
                }
            }
        }

        const int col = n0 + tn * 4;
        const float4 bz = *reinterpret_cast<const float4*>(bias + col);
#pragma unroll
        for (int i = 0; i < 2; i++) {
            const size_t row = m0 + 2 * tm + i;
            float4 o;
            o.x = acc[i][0] + bz.x;
            o.y = acc[i][1] + bz.y;
            o.z = acc[i][2] + bz.z;
            o.w = acc[i][3] + bz.w;
            *reinterpret_cast<float4*>(out + row * Vv + col) = o;
        }
    }
}

// Defensive tail: append lengths if harness packs the whole tuple.
__global__ void joiner_tail_kernel(const int* __restrict__ src_len,
                                   const int* __restrict__ tgt_len,
                                   float* __restrict__ out, int extras) {
    int i = threadIdx.x;
    if (i < extras) {
        size_t base = (size_t)Mm * Vv;
        if (i < Bb) out[base + i] = (float)src_len[i];
        else if (i < 2 * Bb) out[base + i] = (float)tgt_len[i - Bb];
        else out[base + i] = 0.0f;
    }
}

extern "C" void kernel_launch(void* const* d_in, const int* in_sizes, int n_in,
                              void* d_out, int out_size) {
    const float* src     = (const float*)d_in[0];
    const int*   src_len = (const int*)d_in[1];
    const float* tgt     = (const float*)d_in[2];
    const int*   tgt_len = (const int*)d_in[3];
    const float* W       = (const float*)d_in[4];
    const float* bias    = (const float*)d_in[5];
    float* out = (float*)d_out;

    prep_a_kernel<<<(unsigned)(Mm * (Dd / 16) / 256), 256>>>(src, tgt);
    prep_w_kernel<<<(Vv * Dd / 8) / 256, 256>>>(W);

    cudaFuncSetAttribute(joiner_gemm_hybrid,
                         cudaFuncAttributeMaxDynamicSharedMemorySize, SMEM_TOTAL);
    dim3 grid(NT_CTAS + (BN / BNF), (unsigned)(Mm / BM));   // 15 x 1250
    joiner_gemm_hybrid<<<grid, 256, SMEM_TOTAL>>>(W, bias, out);

    long long extras = (long long)out_size - (long long)Mm * Vv;
    if (extras > 0) {
        int e = (int)(extras > 64 ? 64 : extras);
        joiner_tail_kernel<<<1, 64>>>(src_len, tgt_len, out, e);
    }
}

// round 11
// speedup vs baseline: 1.9570x; 1.9570x over previous
#include <cuda_runtime.h>
#include <cuda_fp16.h>
#include <cstdint>

// RNN-T Joiner, fp16 tensor-core path. R11: consolidated prep (A+W+tail in one
// launch) + R7 GEMM (at the legacy-HMMA rt=16 issue floor) unchanged.
// M = 160000, K = 512, N = 1024.

constexpr int Bb = 4, Tt = 400, Uu = 100, Dd = 512, Vv = 1024;
constexpr long long Mm = (long long)Bb * Tt * Uu;   // 160000 = 128*1250

#define BM 128
#define BN 128
#define BK 32
#define NCH (Dd / BK)        // 16
#define STG 4                // cp.async stages
#define RST 40               // smem row stride in halfs (80B): conflict-free

__device__ __half A_half[(size_t)Mm * Dd];   // 164 MB scratch (sanctioned)
__device__ __half W_half[(size_t)Vv * Dd];   // 1 MB

constexpr int NA_BLOCKS = (int)(Mm * Dd / 32 / 256);        // 10000
constexpr int NW_BLOCKS = (Vv * Dd / 8) / 256;              // 256

__device__ __forceinline__ float fast_tanh(float x) {
    float y; asm("tanh.approx.f32 %0, %1;" : "=f"(y) : "f"(x)); return y;
}
__device__ __forceinline__ uint32_t smem_u32(const void* p) {
    uint32_t a;
    asm("{ .reg .u64 t; cvta.to.shared.u64 t, %1; cvt.u32.u64 %0, t; }" : "=r"(a) : "l"(p));
    return a;
}
__device__ __forceinline__ void mma_fp16(float* d, const uint32_t* a,
                                         uint32_t b0, uint32_t b1) {
    asm volatile(
        "mma.sync.aligned.m16n8k16.row.col.f32.f16.f16.f32 "
        "{%0,%1,%2,%3}, {%4,%5,%6,%7}, {%8,%9}, {%0,%1,%2,%3};"
        : "+f"(d[0]), "+f"(d[1]), "+f"(d[2]), "+f"(d[3])
        : "r"(a[0]), "r"(a[1]), "r"(a[2]), "r"(a[3]), "r"(b0), "r"(b1));
}
__device__ __forceinline__ void ldm_x4(uint32_t* r, uint32_t addr) {
    asm volatile("ldmatrix.sync.aligned.m8n8.x4.shared.b16 {%0,%1,%2,%3}, [%4];"
                 : "=r"(r[0]), "=r"(r[1]), "=r"(r[2]), "=r"(r[3]) : "r"(addr));
}

// ---------------- Phase 1: A(tanh->fp16), W->fp16, tail, one launch --------
__global__ __launch_bounds__(256)
void prep_all_kernel(const float* __restrict__ src, const float* __restrict__ tgt,
                     const float* __restrict__ W,
                     const int* __restrict__ src_len, const int* __restrict__ tgt_len,
                     float* __restrict__ out, int extras) {
    const int bid = blockIdx.x;
    const int tid = threadIdx.x;
    if (bid < NA_BLOCKS) {
        // A: 32 elems (one 64B fp16 segment) per thread
        size_t idx = (size_t)bid * 256 + tid;
        int m = (int)(idx >> 4);
        int kv = ((int)idx & 15) * 32;
        int b = m / (Tt * Uu);
        int rem = m - b * (Tt * Uu);
        int t = rem / Uu;
        int u = rem - t * Uu;
        const float* sp = src + ((size_t)b * Tt + t) * Dd + kv;
        const float* tp = tgt + ((size_t)b * Uu + u) * Dd + kv;
        __half* dst = &A_half[(size_t)m * Dd + kv];
#pragma unroll
        for (int seg = 0; seg < 4; seg++) {       // 8 elems per segment
            float4 s0 = *reinterpret_cast<const float4*>(sp + seg * 8);
            float4 s1 = *reinterpret_cast<const float4*>(sp + seg * 8 + 4);
            float4 t0 = *reinterpret_cast<const float4*>(tp + seg * 8);
            float4 t1 = *reinterpret_cast<const float4*>(tp + seg * 8 + 4);
            __half2 h[4];
            h[0] = __floats2half2_rn(fast_tanh(s0.x + t0.x), fast_tanh(s0.y + t0.y));
            h[1] = __floats2half2_rn(fast_tanh(s0.z + t0.z), fast_tanh(s0.w + t0.w));
            h[2] = __floats2half2_rn(fast_tanh(s1.x + t1.x), fast_tanh(s1.y + t1.y));
            h[3] = __floats2half2_rn(fast_tanh(s1.z + t1.z), fast_tanh(s1.w + t1.w));
            *reinterpret_cast<uint4*>(dst + seg * 8) = *reinterpret_cast<uint4*>(h);
        }
    } else if (bid < NA_BLOCKS + NW_BLOCKS) {
        // W -> fp16: 8 floats per thread
        size_t idx = ((size_t)(bid - NA_BLOCKS) * 256 + tid) * 8;
        float4 w0 = *reinterpret_cast<const float4*>(W + idx);
        float4 w1 = *reinterpret_cast<const float4*>(W + idx + 4);
        __half2 h[4];
        h[0] = __floats2half2_rn(w0.x, w0.y);
        h[1] = __floats2half2_rn(w0.z, w0.w);
        h[2] = __floats2half2_rn(w1.x, w1.y);
        h[3] = __floats2half2_rn(w1.z, w1.w);
        *reinterpret_cast<uint4*>(&W_half[idx]) = *reinterpret_cast<uint4*>(h);
    } else {
        // tail: append lengths if harness packs the whole tuple
        if (tid < extras) {
            size_t base = (size_t)Mm * Vv;
            if (tid < Bb) out[base + tid] = (float)src_len[tid];
            else if (tid < 2 * Bb) out[base + tid] = (float)tgt_len[tid - Bb];
            else out[base + tid] = 0.0f;
        }
    }
}

// ---------------- Phase 2: fp16 GEMM (identical to R7 best) ----------------
constexpr int STAGE_H = BM * RST;                   // 5120 halfs / stage
constexpr int SMEM_TOTAL = 2 * STG * STAGE_H * 2;   // A + B = 81920 B

__global__ __launch_bounds__(256, 2)
void joiner_gemm_fp16(const float* __restrict__ bias, float* __restrict__ out) {
    extern __shared__ __half sm[];
    __half* Asm = sm;
    __half* Bsm = sm + STG * STAGE_H;

    const int tid = threadIdx.x;
    const int wid = tid >> 5, lid = tid & 31;
    const int g = lid >> 2, c = lid & 3;
    const int wm = wid >> 2, wn = wid & 3;           // warp grid 2(m) x 4(n)
    // n-block fastest -> 8 CTAs share one A m-chunk in L2
    const size_t m0 = (size_t)blockIdx.y * BM;
    const int n0 = blockIdx.x * BN;

    const int r = tid >> 1;
    const int h = tid & 1;
    const __half* agp = A_half + (m0 + r) * Dd + h * 16;
    const __half* bgp = W_half + (size_t)(n0 + r) * Dd + h * 16;
    const uint32_t a_dst0 = smem_u32(Asm) + (uint32_t)(r * (RST * 2) + h * 32);
    const uint32_t b_dst0 = smem_u32(Bsm) + (uint32_t)(r * (RST * 2) + h * 32);

    const uint32_t a_lm = smem_u32(Asm)
        + (uint32_t)((wm * 64 + (lid & 15)) * (RST * 2) + ((lid >> 4) & 1) * 16);
    const uint32_t b_lm = smem_u32(Bsm)
        + (uint32_t)((wn * 32 + ((lid >> 4) & 1) * 8 + (lid & 7)) * (RST * 2)
                     + ((lid >> 3) & 1) * 16);

    float acc[4][4][4];
#pragma unroll
    for (int mt = 0; mt < 4; mt++)
#pragma unroll
        for (int nt = 0; nt < 4; nt++)
#pragma unroll
            for (int i = 0; i < 4; i++) acc[mt][nt][i] = 0.0f;

#define ISSUE_STAGE(CH) do {                                                    \
        int st_ = (CH) & (STG - 1);                                             \
        const __half* ag_ = agp + (CH) * BK;                                    \
        const __half* bg_ = bgp + (CH) * BK;                                    \
        uint32_t ad_ = a_dst0 + st_ * (STAGE_H * 2);                            \
        uint32_t bd_ = b_dst0 + st_ * (STAGE_H * 2);                            \
        asm volatile(                                                           \
            "cp.async.cg.shared.global [%0], [%1], 16;\n"                       \
            "cp.async.cg.shared.global [%2], [%3], 16;\n"                       \
            "cp.async.cg.shared.global [%4], [%5], 16;\n"                       \
            "cp.async.cg.shared.global [%6], [%7], 16;\n"                       \
            "cp.async.commit_group;"                                            \
            :: "r"(ad_), "l"(ag_), "r"(ad_ + 16), "l"(ag_ + 8),                 \
               "r"(bd_), "l"(bg_), "r"(bd_ + 16), "l"(bg_ + 8) : "memory");     \
    } while (0)

    ISSUE_STAGE(0); ISSUE_STAGE(1); ISSUE_STAGE(2);

    for (int ch = 0; ch < NCH; ch++) {
        const int rem = NCH - 1 - ch;
        if (rem >= 2)      asm volatile("cp.async.wait_group 2;" ::: "memory");
        else if (rem == 1) asm volatile("cp.async.wait_group 1;" ::: "memory");
        else               asm volatile("cp.async.wait_group 0;" ::: "memory");
        __syncthreads();
        if (ch + 3 < NCH) ISSUE_STAGE(ch + 3);

        const int st = ch & (STG - 1);
        const uint32_t a_st = a_lm + st * (STAGE_H * 2);
        const uint32_t b_st = b_lm + st * (STAGE_H * 2);
#pragma unroll
        for (int ks = 0; ks < 2; ks++) {
            const int kbB = ks * 32;   // byte offset: 16 halfs
            uint32_t a[4][4];
#pragma unroll
            for (int mt = 0; mt < 4; mt++)
                ldm_x4(a[mt], a_st + mt * 16 * (RST * 2) + kbB);
            uint32_t b[2][4];
            ldm_x4(b[0], b_st + kbB);                    // nt 0,1
            ldm_x4(b[1], b_st + 16 * (RST * 2) + kbB);   // nt 2,3
#pragma unroll
            for (int nt = 0; nt < 4; nt++) {
                uint32_t b0 = b[nt >> 1][(nt & 1) * 2];
                uint32_t b1 = b[nt >> 1][(nt & 1) * 2 + 1];
#pragma unroll
                for (int mt = 0; mt < 4; mt++)
                    mma_fp16(acc[mt][nt], a[mt], b0, b1);
            }
        }
    }

    // ---- epilogue: bias + float2 stores ----
#pragma unroll
    for (int nt = 0; nt < 4; nt++) {
        const int col = n0 + wn * 32 + nt * 8 + 2 * c;
        const float2 bz = *reinterpret_cast<const float2*>(bias + col);
#pragma unroll
        for (int mt = 0; mt < 4; mt++) {
            const size_t row = m0 + wm * 64 + mt * 16 + g;
            float2 o1, o2;
            o1.x = acc[mt][nt][0] + bz.x;
            o1.y = acc[mt][nt][1] + bz.y;
            o2.x = acc[mt][nt][2] + bz.x;
            o2.y = acc[mt][nt][3] + bz.y;
            *reinterpret_cast<float2*>(out + row * Vv + col) = o1;
            *reinterpret_cast<float2*>(out + (row + 8) * Vv + col) = o2;
        }
    }
}

extern "C" void kernel_launch(void* const* d_in, const int* in_sizes, int n_in,
                              void* d_out, int out_size) {
    const float* src     = (const float*)d_in[0];
    const int*   src_len = (const int*)d_in[1];
    const float* tgt     = (const float*)d_in[2];
    const int*   tgt_len = (const int*)d_in[3];
    const float* W       = (const float*)d_in[4];
    const float* bias    = (const float*)d_in[5];
    float* out = (float*)d_out;

    long long extras_ll = (long long)out_size - (long long)Mm * Vv;
    int extras = (int)(extras_ll < 0 ? 0 : (extras_ll > 256 ? 256 : extras_ll));

    prep_all_kernel<<<NA_BLOCKS + NW_BLOCKS + 1, 256>>>(
        src, tgt, W, src_len, tgt_len, out, extras);

    cudaFuncSetAttribute(joiner_gemm_fp16,
                         cudaFuncAttributeMaxDynamicSharedMemorySize, SMEM_TOTAL);
    dim3 grid(Vv / BN, (unsigned)(Mm / BM));   // 8 x 1250, n fastest
    joiner_gemm_fp16<<<grid, 256, SMEM_TOTAL>>>(bias, out);
}

// round 12
// speedup vs baseline: 1.9830x; 1.0133x over previous
#include <cuda_runtime.h>
#include <cuda_fp16.h>
#include <cstdint>

// RNN-T Joiner, fp16 tensor-core path. R12: persistent-CTA GEMM (304 CTAs,
// continuous cp.async ring across tiles) + R7-mapping prep in one launch.
// M = 160000, K = 512, N = 1024. Legacy HMMA measured rt=8 (tensor=48.8% in
// R11) -> attack stall time: pay pipeline prologue once per CTA, overlap
// epilogue with next tile's loads.

constexpr int Bb = 4, Tt = 400, Uu = 100, Dd = 512, Vv = 1024;
constexpr long long Mm = (long long)Bb * Tt * Uu;   // 160000 = 128*1250

#define BM 128
#define BN 128
#define BK 32
#define NCH (Dd / BK)        // 16
#define STG 4                // cp.async ring stages
#define RST 40               // smem row stride in halfs (80B): conflict-free
#define GRID 304             // persistent CTAs (2 per SM on 152 SMs)

constexpr int NTILES = (int)(Mm / BM) * (Vv / BN);   // 10000

__device__ __half A_half[(size_t)Mm * Dd];   // 164 MB scratch (sanctioned)
__device__ __half W_half[(size_t)Vv * Dd];   // 1 MB

constexpr int NA_BLOCKS = (int)(Mm * Dd / 8 / 256);   // 40000 (8 elems/thread)
constexpr int NW_BLOCKS = (Vv * Dd / 8) / 256;        // 256

__device__ __forceinline__ float fast_tanh(float x) {
    float y; asm("tanh.approx.f32 %0, %1;" : "=f"(y) : "f"(x)); return y;
}
__device__ __forceinline__ uint32_t smem_u32(const void* p) {
    uint32_t a;
    asm("{ .reg .u64 t; cvta.to.shared.u64 t, %1; cvt.u32.u64 %0, t; }" : "=r"(a) : "l"(p));
    return a;
}
__device__ __forceinline__ void mma_fp16(float* d, const uint32_t* a,
                                         uint32_t b0, uint32_t b1) {
    asm volatile(
        "mma.sync.aligned.m16n8k16.row.col.f32.f16.f16.f32 "
        "{%0,%1,%2,%3}, {%4,%5,%6,%7}, {%8,%9}, {%0,%1,%2,%3};"
        : "+f"(d[0]), "+f"(d[1]), "+f"(d[2]), "+f"(d[3])
        : "r"(a[0]), "r"(a[1]), "r"(a[2]), "r"(a[3]), "r"(b0), "r"(b1));
}
__device__ __forceinline__ void ldm_x4(uint32_t* r, uint32_t addr) {
    asm volatile("ldmatrix.sync.aligned.m8n8.x4.shared.b16 {%0,%1,%2,%3}, [%4];"
                 : "=r"(r[0]), "=r"(r[1]), "=r"(r[2]), "=r"(r[3]) : "r"(addr));
}

// ------- Phase 1: A(tanh->fp16) [R7 8-elem mapping], W->fp16, tail --------
__global__ __launch_bounds__(256)
void prep_all_kernel(const float* __restrict__ src, const float* __restrict__ tgt,
                     const float* __restrict__ W,
                     const int* __restrict__ src_len, const int* __restrict__ tgt_len,
                     float* __restrict__ out, int extras) {
    const int bid = blockIdx.x;
    const int tid = threadIdx.x;
    if (bid < NA_BLOCKS) {
        size_t idx = (size_t)bid * 256 + tid;     // one per 8 elems
        int m = (int)(idx >> 6);
        int kv = ((int)idx & 63) * 8;
        int b = m / (Tt * Uu);
        int rem = m - b * (Tt * Uu);
        int t = rem / Uu;
        int u = rem - t * Uu;
        const float* sp = src + ((size_t)b * Tt + t) * Dd + kv;
        const float* tp = tgt + ((size_t)b * Uu + u) * Dd + kv;
        float4 s0 = *reinterpret_cast<const float4*>(sp);
        float4 s1 = *reinterpret_cast<const float4*>(sp + 4);
        float4 t0 = *reinterpret_cast<const float4*>(tp);
        float4 t1 = *reinterpret_cast<const float4*>(tp + 4);
        __half2 h[4];
        h[0] = __floats2half2_rn(fast_tanh(s0.x + t0.x), fast_tanh(s0.y + t0.y));
        h[1] = __floats2half2_rn(fast_tanh(s0.z + t0.z), fast_tanh(s0.w + t0.w));
        h[2] = __floats2half2_rn(fast_tanh(s1.x + t1.x), fast_tanh(s1.y + t1.y));
        h[3] = __floats2half2_rn(fast_tanh(s1.z + t1.z), fast_tanh(s1.w + t1.w));
        *reinterpret_cast<uint4*>(&A_half[(size_t)m * Dd + kv]) =
            *reinterpret_cast<uint4*>(h);
    } else if (bid < NA_BLOCKS + NW_BLOCKS) {
        size_t idx = ((size_t)(bid - NA_BLOCKS) * 256 + tid) * 8;
        float4 w0 = *reinterpret_cast<const float4*>(W + idx);
        float4 w1 = *reinterpret_cast<const float4*>(W + idx + 4);
        __half2 h[4];
        h[0] = __floats2half2_rn(w0.x, w0.y);
        h[1] = __floats2half2_rn(w0.z, w0.w);
        h[2] = __floats2half2_rn(w1.x, w1.y);
        h[3] = __floats2half2_rn(w1.z, w1.w);
        *reinterpret_cast<uint4*>(&W_half[idx]) = *reinterpret_cast<uint4*>(h);
    } else {
        if (tid < extras) {
            size_t base = (size_t)Mm * Vv;
            if (tid < Bb) out[base + tid] = (float)src_len[tid];
            else if (tid < 2 * Bb) out[base + tid] = (float)tgt_len[tid - Bb];
            else out[base + tid] = 0.0f;
        }
    }
}

// ---------------- Phase 2: persistent fp16 GEMM ----------------
constexpr int STAGE_H = BM * RST;                   // 5120 halfs / stage
constexpr int SMEM_TOTAL = 2 * STG * STAGE_H * 2;   // A + B = 81920 B

__global__ __launch_bounds__(256, 2)
void joiner_gemm_persistent(const float* __restrict__ bias, float* __restrict__ out) {
    extern __shared__ __half sm[];
    __half* Asm = sm;
    __half* Bsm = sm + STG * STAGE_H;

    const int tid = threadIdx.x;
    const int wid = tid >> 5, lid = tid & 31;
    const int g = lid >> 2, c = lid & 3;
    const int wm = wid >> 2, wn = wid & 3;           // warp grid 2(m) x 4(n)
    const int bx0 = blockIdx.x;

    // producer mapping: 2 threads per row, 16 halfs (32B) each
    const int r = tid >> 1;
    const int h = tid & 1;
    const uint32_t a_dst0 = smem_u32(Asm) + (uint32_t)(r * (RST * 2) + h * 32);
    const uint32_t b_dst0 = smem_u32(Bsm) + (uint32_t)(r * (RST * 2) + h * 32);

    // ldmatrix per-lane source addresses (stage 0 base)
    const uint32_t a_lm = smem_u32(Asm)
        + (uint32_t)((wm * 64 + (lid & 15)) * (RST * 2) + ((lid >> 4) & 1) * 16);
    const uint32_t b_lm = smem_u32(Bsm)
        + (uint32_t)((wn * 32 + ((lid >> 4) & 1) * 8 + (lid & 7)) * (RST * 2)
                     + ((lid >> 3) & 1) * 16);

    // tiles for this CTA: gt = bx0 + j*GRID, j = 0..J-1 (n = gt&7 fastest)
    const int J = (NTILES - bx0 + GRID - 1) / GRID;
    const int total_ch = J * NCH;

    float acc[4][4][4];
#pragma unroll
    for (int mt = 0; mt < 4; mt++)
#pragma unroll
        for (int nt = 0; nt < 4; nt++)
#pragma unroll
            for (int i = 0; i < 4; i++) acc[mt][nt][i] = 0.0f;

#define ISSUE_CHUNK(P) do {                                                     \
        int gt_ = bx0 + ((P) >> 4) * GRID;                                      \
        const __half* ag_ = A_half + ((size_t)(gt_ >> 3) * BM + r) * Dd         \
                            + ((P) & 15) * BK + h * 16;                         \
        const __half* bg_ = W_half + ((size_t)((gt_ & 7) * BN + r)) * Dd        \
                            + ((P) & 15) * BK + h * 16;                         \
        uint32_t ad_ = a_dst0 + ((P) & 3) * (STAGE_H * 2);                      \
        uint32_t bd_ = b_dst0 + ((P) & 3) * (STAGE_H * 2);                      \
        asm volatile(                                                           \
            "cp.async.cg.shared.global [%0], [%1], 16;\n"                       \
            "cp.async.cg.shared.global [%2], [%3], 16;\n"                       \
            "cp.async.cg.shared.global [%4], [%5], 16;\n"                       \
            "cp.async.cg.shared.global [%6], [%7], 16;\n"                       \
            "cp.async.commit_group;"                                            \
            :: "r"(ad_), "l"(ag_), "r"(ad_ + 16), "l"(ag_ + 8),                 \
               "r"(bd_), "l"(bg_), "r"(bd_ + 16), "l"(bg_ + 8) : "memory");     \
    } while (0)

    // prologue: fill 3 of 4 ring slots (paid ONCE per CTA)
    int pi = 0;
    for (; pi < 3 && pi < total_ch; pi++) ISSUE_CHUNK(pi);

    for (int p = 0; p < total_ch; p++) {
        const int pending = pi - p - 1;   // groups allowed to stay in flight
        if (pending >= 2)      asm volatile("cp.async.wait_group 2;" ::: "memory");
        else if (pending == 1) asm volatile("cp.async.wait_group 1;" ::: "memory");
        else                   asm volatile("cp.async.wait_group 0;" ::: "memory");
        __syncthreads();
        if (pi < total_ch) { ISSUE_CHUNK(pi); pi++; }

        const int st = p & 3;
        const uint32_t a_st = a_lm + st * (STAGE_H * 2);
        const uint32_t b_st = b_lm + st * (STAGE_H * 2);
#pragma unroll
        for (int ks = 0; ks < 2; ks++) {
            const int kbB = ks * 32;
            uint32_t a[4][4];
#pragma unroll
            for (int mt = 0; mt < 4; mt++)
                ldm_x4(a[mt], a_st + mt * 16 * (RST * 2) + kbB);
            uint32_t b[2][4];
            ldm_x4(b[0], b_st + kbB);
            ldm_x4(b[1], b_st + 16 * (RST * 2) + kbB);
#pragma unroll
            for (int nt = 0; nt < 4; nt++) {
                uint32_t b0 = b[nt >> 1][(nt & 1) * 2];
                uint32_t b1 = b[nt >> 1][(nt & 1) * 2 + 1];
#pragma unroll
                for (int mt = 0; mt < 4; mt++)
                    mma_fp16(acc[mt][nt], a[mt], b0, b1);
            }
        }

        if ((p & 15) == 15) {
            // epilogue for completed tile; next tile's loads already in flight
            const int gt = bx0 + (p >> 4) * GRID;
            const size_t m0 = (size_t)(gt >> 3) * BM;
            const int n0 = (gt & 7) * BN;
#pragma unroll
            for (int nt = 0; nt < 4; nt++) {
                const int col = n0 + wn * 32 + nt * 8 + 2 * c;
                const float2 bz = *reinterpret_cast<const float2*>(bias + col);
#pragma unroll
                for (int mt = 0; mt < 4; mt++) {
                    const size_t row = m0 + wm * 64 + mt * 16 + g;
                    float2 o1, o2;
                    o1.x = acc[mt][nt][0] + bz.x;
                    o1.y = acc[mt][nt][1] + bz.y;
                    o2.x = acc[mt][nt][2] + bz.x;
                    o2.y = acc[mt][nt][3] + bz.y;
                    *reinterpret_cast<float2*>(out + row * Vv + col) = o1;
                    *reinterpret_cast<float2*>(out + (row + 8) * Vv + col) = o2;
                    acc[mt][nt][0] = 0.0f; acc[mt][nt][1] = 0.0f;
                    acc[mt][nt][2] = 0.0f; acc[mt][nt][3] = 0.0f;
                }
            }
        }
    }
}

extern "C" void kernel_launch(void* const* d_in, const int* in_sizes, int n_in,
                              void* d_out, int out_size) {
    const float* src     = (const float*)d_in[0];
    const int*   src_len = (const int*)d_in[1];
    const float* tgt     = (const float*)d_in[2];
    const int*   tgt_len = (const int*)d_in[3];
    const float* W       = (const float*)d_in[4];
    const float* bias    = (const float*)d_in[5];
    float* out = (float*)d_out;

    long long extras_ll = (long long)out_size - (long long)Mm * Vv;
    int extras = (int)(extras_ll < 0 ? 0 : (extras_ll > 256 ? 256 : extras_ll));

    prep_all_kernel<<<NA_BLOCKS + NW_BLOCKS + 1, 256>>>(
        src, tgt, W, src_len, tgt_len, out, extras);

    cudaFuncSetAttribute(joiner_gemm_persistent,
                         cudaFuncAttributeMaxDynamicSharedMemorySize, SMEM_TOTAL);
    joiner_gemm_persistent<<<GRID, 256, SMEM_TOTAL>>>(bias, out);
}

// round 13
// speedup vs baseline: 2.0597x; 1.0387x over previous
#include <cuda_runtime.h>
#include <cuda_fp16.h>
#include <cstdint>

// RNN-T Joiner, fp16 tensor-core path. R13: flat grid (R11 GEMM structure),
// BK=64 with 2-stage double buffer -> half the barriers/waits per tile.
// prep (A tanh->fp16 R7 mapping, W->fp16, tail) in one launch.
// M = 160000, K = 512, N = 1024.

constexpr int Bb = 4, Tt = 400, Uu = 100, Dd = 512, Vv = 1024;
constexpr long long Mm = (long long)Bb * Tt * Uu;   // 160000 = 128*1250

#define BM 128
#define BN 128
#define BK 64
#define NCH (Dd / BK)        // 8
#define RST 72               // smem row stride in halfs (144B): conflict-free

__device__ __half A_half[(size_t)Mm * Dd];   // 164 MB scratch (sanctioned)
__device__ __half W_half[(size_t)Vv * Dd];   // 1 MB

constexpr int NA_BLOCKS = (int)(Mm * Dd / 8 / 256);   // 40000 (8 elems/thread)
constexpr int NW_BLOCKS = (Vv * Dd / 8) / 256;        // 256

__device__ __forceinline__ float fast_tanh(float x) {
    float y; asm("tanh.approx.f32 %0, %1;" : "=f"(y) : "f"(x)); return y;
}
__device__ __forceinline__ uint32_t smem_u32(const void* p) {
    uint32_t a;
    asm("{ .reg .u64 t; cvta.to.shared.u64 t, %1; cvt.u32.u64 %0, t; }" : "=r"(a) : "l"(p));
    return a;
}
__device__ __forceinline__ void mma_fp16(float* d, const uint32_t* a,
                                         uint32_t b0, uint32_t b1) {
    asm volatile(
        "mma.sync.aligned.m16n8k16.row.col.f32.f16.f16.f32 "
        "{%0,%1,%2,%3}, {%4,%5,%6,%7}, {%8,%9}, {%0,%1,%2,%3};"
        : "+f"(d[0]), "+f"(d[1]), "+f"(d[2]), "+f"(d[3])
        : "r"(a[0]), "r"(a[1]), "r"(a[2]), "r"(a[3]), "r"(b0), "r"(b1));
}
__device__ __forceinline__ void ldm_x4(uint32_t* r, uint32_t addr) {
    asm volatile("ldmatrix.sync.aligned.m8n8.x4.shared.b16 {%0,%1,%2,%3}, [%4];"
                 : "=r"(r[0]), "=r"(r[1]), "=r"(r[2]), "=r"(r[3]) : "r"(addr));
}

// ------- Phase 1: A(tanh->fp16) [R7 8-elem mapping], W->fp16, tail --------
__global__ __launch_bounds__(256)
void prep_all_kernel(const float* __restrict__ src, const float* __restrict__ tgt,
                     const float* __restrict__ W,
                     const int* __restrict__ src_len, const int* __restrict__ tgt_len,
                     float* __restrict__ out, int extras) {
    const int bid = blockIdx.x;
    const int tid = threadIdx.x;
    if (bid < NA_BLOCKS) {
        size_t idx = (size_t)bid * 256 + tid;     // one per 8 elems
        int m = (int)(idx >> 6);
        int kv = ((int)idx & 63) * 8;
        int b = m / (Tt * Uu);
        int rem = m - b * (Tt * Uu);
        int t = rem / Uu;
        int u = rem - t * Uu;
        const float* sp = src + ((size_t)b * Tt + t) * Dd + kv;
        const float* tp = tgt + ((size_t)b * Uu + u) * Dd + kv;
        float4 s0 = *reinterpret_cast<const float4*>(sp);
        float4 s1 = *reinterpret_cast<const float4*>(sp + 4);
        float4 t0 = *reinterpret_cast<const float4*>(tp);
        float4 t1 = *reinterpret_cast<const float4*>(tp + 4);
        __half2 h[4];
        h[0] = __floats2half2_rn(fast_tanh(s0.x + t0.x), fast_tanh(s0.y + t0.y));
        h[1] = __floats2half2_rn(fast_tanh(s0.z + t0.z), fast_tanh(s0.w + t0.w));
        h[2] = __floats2half2_rn(fast_tanh(s1.x + t1.x), fast_tanh(s1.y + t1.y));
        h[3] = __floats2half2_rn(fast_tanh(s1.z + t1.z), fast_tanh(s1.w + t1.w));
        *reinterpret_cast<uint4*>(&A_half[(size_t)m * Dd + kv]) =
            *reinterpret_cast<uint4*>(h);
    } else if (bid < NA_BLOCKS + NW_BLOCKS) {
        size_t idx = ((size_t)(bid - NA_BLOCKS) * 256 + tid) * 8;
        float4 w0 = *reinterpret_cast<const float4*>(W + idx);
        float4 w1 = *reinterpret_cast<const float4*>(W + idx + 4);
        __half2 h[4];
        h[0] = __floats2half2_rn(w0.x, w0.y);
        h[1] = __floats2half2_rn(w0.z, w0.w);
        h[2] = __floats2half2_rn(w1.x, w1.y);
        h[3] = __floats2half2_rn(w1.z, w1.w);
        *reinterpret_cast<uint4*>(&W_half[idx]) = *reinterpret_cast<uint4*>(h);
    } else {
        if (tid < extras) {
            size_t base = (size_t)Mm * Vv;
            if (tid < Bb) out[base + tid] = (float)src_len[tid];
            else if (tid < 2 * Bb) out[base + tid] = (float)tgt_len[tid - Bb];
            else out[base + tid] = 0.0f;
        }
    }
}

// ---------------- Phase 2: fp16 GEMM, BK=64, 2-stage ----------------
constexpr int STAGE_H = BM * RST;                   // 9216 halfs / stage
constexpr int SMEM_TOTAL = 2 * 2 * STAGE_H * 2;     // A + B, 2 stages = 73728 B

__global__ __launch_bounds__(256, 2)
void joiner_gemm_fp16(const float* __restrict__ bias, float* __restrict__ out) {
    extern __shared__ __half sm[];
    __half* Asm = sm;                     // 2 stages
    __half* Bsm = sm + 2 * STAGE_H;       // 2 stages

    const int tid = threadIdx.x;
    const int wid = tid >> 5, lid = tid & 31;
    const int g = lid >> 2, c = lid & 3;
    const int wm = wid >> 2, wn = wid & 3;           // warp grid 2(m) x 4(n)
    // n-block fastest -> 8 CTAs share one A m-chunk in L2
    const size_t m0 = (size_t)blockIdx.y * BM;
    const int n0 = blockIdx.x * BN;

    // producer mapping: 2 threads per row, 32 halfs (64B = 4x16B) each
    const int r = tid >> 1;
    const int h = tid & 1;
    const __half* agp = A_half + (m0 + r) * Dd + h * 32;
    const __half* bgp = W_half + (size_t)(n0 + r) * Dd + h * 32;
    const uint32_t a_dst0 = smem_u32(Asm) + (uint32_t)(r * (RST * 2) + h * 64);
    const uint32_t b_dst0 = smem_u32(Bsm) + (uint32_t)(r * (RST * 2) + h * 64);

    // ldmatrix per-lane source addresses (stage 0 base)
    const uint32_t a_lm = smem_u32(Asm)
        + (uint32_t)((wm * 64 + (lid & 15)) * (RST * 2) + ((lid >> 4) & 1) * 16);
    const uint32_t b_lm = smem_u32(Bsm)
        + (uint32_t)((wn * 32 + ((lid >> 4) & 1) * 8 + (lid & 7)) * (RST * 2)
                     + ((lid >> 3) & 1) * 16);

    float acc[4][4][4];
#pragma unroll
    for (int mt = 0; mt < 4; mt++)
#pragma unroll
        for (int nt = 0; nt < 4; nt++)
#pragma unroll
            for (int i = 0; i < 4; i++) acc[mt][nt][i] = 0.0f;

#define ISSUE_STAGE(CH) do {                                                    \
        int st_ = (CH) & 1;                                                     \
        const __half* ag_ = agp + (CH) * BK;                                    \
        const __half* bg_ = bgp + (CH) * BK;                                    \
        uint32_t ad_ = a_dst0 + st_ * (STAGE_H * 2);                            \
        uint32_t bd_ = b_dst0 + st_ * (STAGE_H * 2);                            \
        asm volatile(                                                           \
            "cp.async.cg.shared.global [%0], [%1], 16;\n"                       \
            "cp.async.cg.shared.global [%2], [%3], 16;\n"                       \
            "cp.async.cg.shared.global [%4], [%5], 16;\n"                       \
            "cp.async.cg.shared.global [%6], [%7], 16;\n"                       \
            "cp.async.cg.shared.global [%8], [%9], 16;\n"                       \
            "cp.async.cg.shared.global [%10], [%11], 16;\n"                     \
            "cp.async.cg.shared.global [%12], [%13], 16;\n"                     \
            "cp.async.cg.shared.global [%14], [%15], 16;\n"                     \
            "cp.async.commit_group;"                                            \
            :: "r"(ad_), "l"(ag_), "r"(ad_ + 16), "l"(ag_ + 8),                 \
               "r"(ad_ + 32), "l"(ag_ + 16), "r"(ad_ + 48), "l"(ag_ + 24),      \
               "r"(bd_), "l"(bg_), "r"(bd_ + 16), "l"(bg_ + 8),                 \
               "r"(bd_ + 32), "l"(bg_ + 16), "r"(bd_ + 48), "l"(bg_ + 24)       \
            : "memory");                                                        \
    } while (0)

    ISSUE_STAGE(0);

#pragma unroll
    for (int ch = 0; ch < NCH; ch++) {
        asm volatile("cp.async.wait_group 0;" ::: "memory");
        __syncthreads();
        if (ch + 1 < NCH) ISSUE_STAGE(ch + 1);

        const int st = ch & 1;
        const uint32_t a_st = a_lm + st * (STAGE_H * 2);
        const uint32_t b_st = b_lm + st * (STAGE_H * 2);
#pragma unroll
        for (int ks = 0; ks < 4; ks++) {
            const int kbB = ks * 32;   // byte offset: 16 halfs per k-step
            uint32_t a[4][4];
#pragma unroll
            for (int mt = 0; mt < 4; mt++)
                ldm_x4(a[mt], a_st + mt * 16 * (RST * 2) + kbB);
            uint32_t b[2][4];
            ldm_x4(b[0], b_st + kbB);                    // nt 0,1
            ldm_x4(b[1], b_st + 16 * (RST * 2) + kbB);   // nt 2,3
#pragma unroll
            for (int nt = 0; nt < 4; nt++) {
                uint32_t b0 = b[nt >> 1][(nt & 1) * 2];
                uint32_t b1 = b[nt >> 1][(nt & 1) * 2 + 1];
#pragma unroll
                for (int mt = 0; mt < 4; mt++)
                    mma_fp16(acc[mt][nt], a[mt], b0, b1);
            }
        }
    }

    // ---- epilogue: bias + float2 stores ----
#pragma unroll
    for (int nt = 0; nt < 4; nt++) {
        const int col = n0 + wn * 32 + nt * 8 + 2 * c;
        const float2 bz = *reinterpret_cast<const float2*>(bias + col);
#pragma unroll
        for (int mt = 0; mt < 4; mt++) {
            const size_t row = m0 + wm * 64 + mt * 16 + g;
            float2 o1, o2;
            o1.x = acc[mt][nt][0] + bz.x;
            o1.y = acc[mt][nt][1] + bz.y;
            o2.x = acc[mt][nt][2] + bz.x;
            o2.y = acc[mt][nt][3] + bz.y;
            *reinterpret_cast<float2*>(out + row * Vv + col) = o1;
            *reinterpret_cast<float2*>(out + (row + 8) * Vv + col) = o2;
        }
    }
}

extern "C" void kernel_launch(void* const* d_in, const int* in_sizes, int n_in,
                              void* d_out, int out_size) {
    const float* src     = (const float*)d_in[0];
    const int*   src_len = (const int*)d_in[1];
    const float* tgt     = (const float*)d_in[2];
    const int*   tgt_len = (const int*)d_in[3];
    const float* W       = (const float*)d_in[4];
    const float* bias    = (const float*)d_in[5];
    float* out = (float*)d_out;

    long long extras_ll = (long long)out_size - (long long)Mm * Vv;
    int extras = (int)(extras_ll < 0 ? 0 : (extras_ll > 256 ? 256 : extras_ll));

    prep_all_kernel<<<NA_BLOCKS + NW_BLOCKS + 1, 256>>>(
        src, tgt, W, src_len, tgt_len, out, extras);

    cudaFuncSetAttribute(joiner_gemm_fp16,
                         cudaFuncAttributeMaxDynamicSharedMemorySize, SMEM_TOTAL);
    dim3 grid(Vv / BN, (unsigned)(Mm / BM));   // 8 x 1250, n fastest
    joiner_gemm_fp16<<<grid, 256, SMEM_TOTAL>>>(bias, out);
}